// round 17
// baseline (speedup 1.0000x reference)
#include <cuda_runtime.h>
#include <math.h>

#define B_   64
#define T_   200
#define TP1_ 201
#define D_   128
#define M_   64
#define NQ_  13523
#define BT_  (B_*T_)          // 12800
#define NMC_ 4                // scan m-chunks (R10 proven)

// ---------------- scratch (no allocation allowed) ----------------
__device__ float g_k  [BT_*D_];
__device__ float g_w  [BT_*M_];
__device__ float g_e  [BT_*D_];
__device__ float g_a  [BT_*D_];
__device__ float g_rp [NMC_*BT_*D_];

__device__ __forceinline__ float sigmoidf_(float x) { return 1.0f/(1.0f+expf(-x)); }

// ---- packed fp32x2 helpers (sm_103a FFMA2 path, PTX-only) ----
__device__ __forceinline__ unsigned long long pack2(float x, float y) {
    unsigned long long r;
    asm("mov.b64 %0, {%1, %2};" : "=l"(r) : "f"(x), "f"(y));
    return r;
}
__device__ __forceinline__ void ffma2(unsigned long long& d, unsigned long long a, unsigned long long b) {
    asm("fma.rn.f32x2 %0, %1, %2, %0;" : "+l"(d) : "l"(a), "l"(b));
}
__device__ __forceinline__ void unpack2(unsigned long long v, float& x, float& y) {
    asm("mov.b64 {%0, %1}, %2;" : "=f"(x), "=f"(y) : "l"(v));
}

// N-packed 4x8 step (wsoft only, proven)
__device__ __forceinline__ void mm_step4(unsigned long long acc[4][4],
                                         const float* sxT, const float* swT,
                                         int k, int ti, int tn) {
    float4 xv = *(const float4*)(sxT + k*68 + ti*4);
    ulonglong2 b0 = *(const ulonglong2*)(swT + k*68 + tn*8);
    ulonglong2 b1 = *(const ulonglong2*)(swT + k*68 + tn*8 + 4);
    unsigned long long a;
    a = pack2(xv.x, xv.x);
    ffma2(acc[0][0],a,b0.x); ffma2(acc[0][1],a,b0.y); ffma2(acc[0][2],a,b1.x); ffma2(acc[0][3],a,b1.y);
    a = pack2(xv.y, xv.y);
    ffma2(acc[1][0],a,b0.x); ffma2(acc[1][1],a,b0.y); ffma2(acc[1][2],a,b1.x); ffma2(acc[1][3],a,b1.y);
    a = pack2(xv.z, xv.z);
    ffma2(acc[2][0],a,b0.x); ffma2(acc[2][1],a,b0.y); ffma2(acc[2][2],a,b1.x); ffma2(acc[2][3],a,b1.y);
    a = pack2(xv.w, xv.w);
    ffma2(acc[3][0],a,b0.x); ffma2(acc[3][1],a,b0.y); ffma2(acc[3][2],a,b1.x); ffma2(acc[3][3],a,b1.y);
}

// swizzled row-major smem addr (floats): row stride 36, 16B-chunk XOR
__device__ __forceinline__ int swz(int r, int k4) {
    return r*36 + (k4 ^ (((r>>2)&7)*4));
}

// =================================================================
// Kernel 1: wsoft (k gather + softmax(k @ Mk^T)). 64x64, 4x8. R5-proven.
// =================================================================
__global__ void __launch_bounds__(128) k_wsoft(const int* __restrict__ q,
                                               const float* __restrict__ k_emb,
                                               const float* __restrict__ Mk) {
    __shared__ __align__(16) float sxT[32*68];
    __shared__ __align__(16) float swT[32*68];
    __shared__ float sc[64*65];
    __shared__ int sq[64];
    const int tid  = threadIdx.x;
    const int row0 = blockIdx.x * 64;
    const int ti = tid & 15, tn = tid >> 4;
    int rA[4], kA[4];
#pragma unroll
    for (int it = 0; it < 4; it++) {
        int idx = it*128 + tid;
        rA[it] = idx >> 3; kA[it] = (idx & 7) << 2;
    }
    if (tid < 64) sq[tid] = q[row0 + tid];
    __syncthreads();

    float4 xr[4], wr[4];
#pragma unroll
    for (int it = 0; it < 4; it++) {
        xr[it] = *(const float4*)(k_emb + (size_t)sq[rA[it]]*D_ + kA[it]);
        wr[it] = *(const float4*)(Mk    + (size_t)rA[it]*D_ + kA[it]);
    }
    unsigned long long acc[4][4] = {};
    for (int kc = 0; kc < 4; kc++) {
        if (kc) __syncthreads();
#pragma unroll
        for (int it = 0; it < 4; it++) {
            int k4 = kA[it], row = rA[it];
            sxT[(k4+0)*68+row]=xr[it].x; sxT[(k4+1)*68+row]=xr[it].y;
            sxT[(k4+2)*68+row]=xr[it].z; sxT[(k4+3)*68+row]=xr[it].w;
            swT[(k4+0)*68+row]=wr[it].x; swT[(k4+1)*68+row]=wr[it].y;
            swT[(k4+2)*68+row]=wr[it].z; swT[(k4+3)*68+row]=wr[it].w;
            *(float4*)(g_k + (size_t)(row0+row)*D_ + kc*32 + k4) = xr[it];
        }
        __syncthreads();
        if (kc < 3) {
            int kk = (kc+1)*32;
#pragma unroll
            for (int it = 0; it < 4; it++) {
                xr[it] = *(const float4*)(k_emb + (size_t)sq[rA[it]]*D_ + kk + kA[it]);
                wr[it] = *(const float4*)(Mk    + (size_t)rA[it]*D_ + kk + kA[it]);
            }
        }
#pragma unroll 8
        for (int k = 0; k < 32; k++) mm_step4(acc, sxT, swT, k, ti, tn);
    }
#pragma unroll
    for (int i = 0; i < 4; i++)
#pragma unroll
        for (int c = 0; c < 4; c++) {
            float lo, hi; unpack2(acc[i][c], lo, hi);
            sc[(ti*4+i)*65 + tn*8 + 2*c]     = lo;
            sc[(ti*4+i)*65 + tn*8 + 2*c + 1] = hi;
        }
    __syncthreads();
    if (tid < 64) {
        float mx = -1e30f;
#pragma unroll
        for (int m = 0; m < M_; m++) mx = fmaxf(mx, sc[tid*65 + m]);
        float s = 0.f;
#pragma unroll
        for (int m = 0; m < M_; m++) { float e = expf(sc[tid*65+m]-mx); sc[tid*65+m]=e; s+=e; }
        float inv = 1.0f / s;
#pragma unroll
        for (int m = 0; m < M_; m++)
            g_w[(size_t)(row0+tid)*M_ + m] = sc[tid*65+m]*inv;
    }
}

// =================================================================
// Kernel 2: e/a GEMM, K-packed FFMA2, row-major smem + STS.128.
// grid (200, 4): y 0,1 = eW halves; y 2,3 = aW halves. 256 thr, 4x4 tiles.
// =================================================================
__global__ void __launch_bounds__(256) k_ea(const int* __restrict__ q, const int* __restrict__ rr,
                                            const float* __restrict__ v_emb,
                                            const float* __restrict__ eW, const float* __restrict__ ebv,
                                            const float* __restrict__ aW, const float* __restrict__ abv) {
    __shared__ __align__(16) float sx[64*36];
    __shared__ __align__(16) float sw[64*36];
    __shared__ int sq[64];
    const int tid  = threadIdx.x;
    const int row0 = blockIdx.x * 64;
    const int yb   = blockIdx.y;
    const int ti = tid & 15, tn = tid >> 4;       // rows ti*4.., cols tn*4..
    const float* W    = (yb < 2) ? eW  : aW;
    const float* bias = (yb < 2) ? ebv : abv;
    const int coloff  = (yb & 1) * 64;

    int rL[2], kL[2];                              // tile-load coords (X and W identical)
#pragma unroll
    for (int it = 0; it < 2; it++) {
        int idx = it*256 + tid;
        rL[it] = idx >> 3; kL[it] = (idx & 7) << 2;
    }
    if (tid < 64) { int row = row0 + tid; sq[tid] = q[row] + NQ_ * rr[row]; }
    __syncthreads();

    float4 xr[2], wr[2];
#pragma unroll
    for (int it = 0; it < 2; it++) {
        xr[it] = *(const float4*)(v_emb + (size_t)sq[rL[it]]*D_ + kL[it]);
        wr[it] = *(const float4*)(W + (size_t)(coloff + rL[it])*D_ + kL[it]);
    }

    const int baseA0 = (ti*4)*36, xorA = (ti & 7)*4;
    const int baseB0 = (tn*4)*36, xorB = (tn & 7)*4;

    unsigned long long acc[4][4] = {};
    for (int kc = 0; kc < 4; kc++) {
        if (kc) __syncthreads();
#pragma unroll
        for (int it = 0; it < 2; it++) {
            *(float4*)(sx + swz(rL[it], kL[it])) = xr[it];
            *(float4*)(sw + swz(rL[it], kL[it])) = wr[it];
        }
        __syncthreads();
        if (kc < 3) {
            int kk = (kc+1)*32;
#pragma unroll
            for (int it = 0; it < 2; it++) {
                xr[it] = *(const float4*)(v_emb + (size_t)sq[rL[it]]*D_ + kk + kL[it]);
                wr[it] = *(const float4*)(W + (size_t)(coloff + rL[it])*D_ + kk + kL[it]);
            }
        }
#pragma unroll
        for (int kq = 0; kq < 8; kq++) {
            int k4 = kq*4;
            ulonglong2 a2[4], b2[4];
#pragma unroll
            for (int i = 0; i < 4; i++)
                a2[i] = *(const ulonglong2*)(sx + baseA0 + i*36 + (k4 ^ xorA));
#pragma unroll
            for (int c = 0; c < 4; c++)
                b2[c] = *(const ulonglong2*)(sw + baseB0 + c*36 + (k4 ^ xorB));
#pragma unroll
            for (int i = 0; i < 4; i++)
#pragma unroll
                for (int c = 0; c < 4; c++) {
                    ffma2(acc[i][c], a2[i].x, b2[c].x);
                    ffma2(acc[i][c], a2[i].y, b2[c].y);
                }
        }
    }

    const int n0 = coloff + tn*4;
    float b[4];
#pragma unroll
    for (int c = 0; c < 4; c++) b[c] = bias[n0+c];
    float* gout = (yb < 2) ? g_e : g_a;
#pragma unroll
    for (int i = 0; i < 4; i++) {
        float y[4];
#pragma unroll
        for (int c = 0; c < 4; c++) {
            float lo, hi; unpack2(acc[i][c], lo, hi);
            y[c] = lo + hi + b[c];
        }
        float4 o;
        if (yb < 2) { o.x=sigmoidf_(y[0]); o.y=sigmoidf_(y[1]); o.z=sigmoidf_(y[2]); o.w=sigmoidf_(y[3]); }
        else        { o.x=tanhf(y[0]);     o.y=tanhf(y[1]);     o.z=tanhf(y[2]);     o.w=tanhf(y[3]); }
        *(float4*)(gout + (size_t)(row0 + ti*4 + i)*D_ + n0) = o;
    }
}

// =================================================================
// Kernel 3: sequential scan — R10 proven config. grid (B, 4), 128 thr.
// =================================================================
__global__ void __launch_bounds__(128) k_scan(const float* __restrict__ Mv0, float* __restrict__ out) {
    const int b   = blockIdx.x;
    const int mc  = blockIdx.y;
    const int tid = threadIdx.x;   // d
    const int m0  = mc * 16;
    float Mv[16];

    float* mvout = out + BT_ + (size_t)b * TP1_ * M_ * D_;
#pragma unroll
    for (int i = 0; i < 16; i++) {
        float v = Mv0[(m0 + i) * D_ + tid];
        Mv[i] = v;
        __stcs(mvout + (size_t)(m0 + i) * D_ + tid, v);   // t = 0 slice
    }

    const float* wb  = g_w + (size_t)b * T_ * M_ + m0;
    const float* ebp = g_e + (size_t)b * T_ * D_ + tid;
    const float* abp = g_a + (size_t)b * T_ * D_ + tid;
    float* rp = g_rp + (size_t)mc * BT_ * D_ + (size_t)b * T_ * D_ + tid;

    float4 w0 = *(const float4*)(wb);
    float4 w1 = *(const float4*)(wb + 4);
    float4 w2 = *(const float4*)(wb + 8);
    float4 w3 = *(const float4*)(wb + 12);
    float ecur = ebp[0], acur = abp[0];
    float* orow = mvout + (size_t)M_ * D_ + (size_t)m0 * D_ + tid;

    for (int t = 0; t < T_; t++) {
        float4 nw0=w0, nw1=w1, nw2=w2, nw3=w3;
        float enx = ecur, anx = acur;
        if (t + 1 < T_) {
            const float* wn = wb + (size_t)(t+1)*M_;
            nw0 = *(const float4*)(wn);     nw1 = *(const float4*)(wn + 4);
            nw2 = *(const float4*)(wn + 8); nw3 = *(const float4*)(wn + 12);
            enx = ebp[(size_t)(t+1)*D_];
            anx = abp[(size_t)(t+1)*D_];
        }
        float wv[16] = {w0.x,w0.y,w0.z,w0.w, w1.x,w1.y,w1.z,w1.w,
                        w2.x,w2.y,w2.z,w2.w, w3.x,w3.y,w3.z,w3.w};
        float r0=0.f, r1=0.f;
#pragma unroll
        for (int i = 0; i < 16; i++) {
            float wvi = wv[i];
            if (i & 1) r1 = fmaf(wvi, Mv[i], r1); else r0 = fmaf(wvi, Mv[i], r0);
            Mv[i] = fmaf(wvi, acur, Mv[i] * fmaf(-wvi, ecur, 1.0f));    // Mv*(1-w e)+w a
            __stcs(orow + (size_t)i * D_, Mv[i]);
        }
        rp[(size_t)t * D_] = r0 + r1;
        w0=nw0; w1=nw1; w2=nw2; w3=nw3;
        ecur = enx; acur = anx;
        orow += (size_t)M_ * D_;
    }
}

// =================================================================
// Kernel 4: read = sum(rp); f = tanh([read,k]@fW^T+fb); p = sigmoid(f.pW+pb).
// K-packed FFMA2. 32 rows x 128 cols per CTA (grid 400), 256 thr, 4x4 tiles.
// =================================================================
__global__ void __launch_bounds__(256) k_fp(const float* __restrict__ fW, const float* __restrict__ fb,
                                            const float* __restrict__ pW, const float* __restrict__ pb,
                                            float* __restrict__ out) {
    __shared__ __align__(16) float sx[32*36];
    __shared__ __align__(16) float sw[128*36];
    __shared__ float sp[32*33];
    const int tid  = threadIdx.x;
    const int row0 = blockIdx.x * 32;
    const int ti = tid & 7, tn = tid >> 3;        // rows ti*4 (0..31), cols tn*4 (0..127)

    const int rX = tid >> 3, kX = (tid & 7) << 2; // X-tile load coords (1 per thread)
    int nW[4], kW[4];
#pragma unroll
    for (int it = 0; it < 4; it++) {
        int idx = it*256 + tid;
        nW[it] = idx >> 3; kW[it] = (idx & 7) << 2;
    }

    auto loadX = [&](int row, int kk) -> float4 {
        if (kk < 128) {
            size_t g = (size_t)(row0+row)*D_ + kk;
            float4 v = *(const float4*)(g_rp + g);
#pragma unroll
            for (int j = 1; j < NMC_; j++) {
                float4 a0 = *(const float4*)(g_rp + (size_t)j*BT_*D_ + g);
                v.x += a0.x; v.y += a0.y; v.z += a0.z; v.w += a0.w;
            }
            return v;
        }
        return *(const float4*)(g_k + (size_t)(row0+row)*D_ + (kk-128));
    };

    float4 xr = loadX(rX, kX);
    float4 wr[4];
#pragma unroll
    for (int it = 0; it < 4; it++) wr[it] = *(const float4*)(fW + (size_t)nW[it]*256 + kW[it]);

    const int baseA0 = (ti*4)*36, xorA = ti*4;        // ti<8
    const int baseB0 = (tn*4)*36, xorB = (tn & 7)*4;

    unsigned long long acc[4][4] = {};
    for (int kc = 0; kc < 8; kc++) {
        if (kc) __syncthreads();
        *(float4*)(sx + swz(rX, kX)) = xr;
#pragma unroll
        for (int it = 0; it < 4; it++)
            *(float4*)(sw + swz(nW[it], kW[it])) = wr[it];
        __syncthreads();
        if (kc < 7) {
            int kk = (kc+1)*32;
            xr = loadX(rX, kk + kX);
#pragma unroll
            for (int it = 0; it < 4; it++)
                wr[it] = *(const float4*)(fW + (size_t)nW[it]*256 + kk + kW[it]);
        }
#pragma unroll
        for (int kq = 0; kq < 8; kq++) {
            int k4 = kq*4;
            ulonglong2 a2[4], b2[4];
#pragma unroll
            for (int i = 0; i < 4; i++)
                a2[i] = *(const ulonglong2*)(sx + baseA0 + i*36 + (k4 ^ xorA));
#pragma unroll
            for (int c = 0; c < 4; c++)
                b2[c] = *(const ulonglong2*)(sw + baseB0 + c*36 + (k4 ^ xorB));
#pragma unroll
            for (int i = 0; i < 4; i++)
#pragma unroll
                for (int c = 0; c < 4; c++) {
                    ffma2(acc[i][c], a2[i].x, b2[c].x);
                    ffma2(acc[i][c], a2[i].y, b2[c].y);
                }
        }
    }

    // epilogue: f = tanh(sum + fb), ps = pW . f over this thread's 4 cols
    float ps[4] = {0.f, 0.f, 0.f, 0.f};
#pragma unroll
    for (int c = 0; c < 4; c++) {
        int n = tn*4 + c;
        float bb = fb[n], wp = pW[n];
#pragma unroll
        for (int i = 0; i < 4; i++) {
            float lo, hi; unpack2(acc[i][c], lo, hi);
            ps[i] = fmaf(wp, tanhf(lo + hi + bb), ps[i]);
        }
    }
#pragma unroll
    for (int i = 0; i < 4; i++) sp[(ti*4+i)*33 + tn] = ps[i];
    __syncthreads();
    if (tid < 32) {
        float s = pb[0];
#pragma unroll
        for (int g2 = 0; g2 < 32; g2++) s += sp[tid*33 + g2];
        out[row0 + tid] = 1.0f / (1.0f + expf(-s));
    }
}

// =================================================================
extern "C" void kernel_launch(void* const* d_in, const int* in_sizes, int n_in,
                              void* d_out, int out_size) {
    const int*   q     = (const int*)  d_in[0];
    const int*   r     = (const int*)  d_in[1];
    const float* k_emb = (const float*)d_in[2];
    const float* v_emb = (const float*)d_in[3];
    const float* Mk    = (const float*)d_in[4];
    const float* Mv0   = (const float*)d_in[5];
    const float* fW    = (const float*)d_in[6];
    const float* fb    = (const float*)d_in[7];
    const float* pW    = (const float*)d_in[8];
    const float* pb    = (const float*)d_in[9];
    const float* eW    = (const float*)d_in[10];
    const float* eb    = (const float*)d_in[11];
    const float* aW    = (const float*)d_in[12];
    const float* ab    = (const float*)d_in[13];
    float* out = (float*)d_out;

    k_wsoft<<<BT_/64, 128>>>(q, k_emb, Mk);
    k_ea   <<<dim3(BT_/64, 4), 256>>>(q, r, v_emb, eW, eb, aW, ab);
    k_scan <<<dim3(B_, NMC_), 128>>>(Mv0, out);
    k_fp   <<<BT_/32, 256>>>(fW, fb, pW, pb, out);
}